// round 10
// baseline (speedup 1.0000x reference)
#include <cuda_runtime.h>

#define BATCH 1024
#define TT    512
#define DIN   32
#define H     64
#define NROWS 256
#define BT    (BATCH * TT)
#define HP    68          // padded h row stride (17 float4s, conflict-free)

typedef unsigned long long ull;

// Static scratch: precomputed gate inputs (g_h1 eliminated — h1 never leaves smem).
__device__ float g_xg0[(size_t)BT * NROWS];
__device__ float g_xg1[(size_t)BT * NROWS];

// ---------------------------------------------------------------------------
__device__ __forceinline__ void ffma2(ull& acc, ull w, ull v) {
    asm("fma.rn.f32x2 %0, %1, %2, %0;" : "+l"(acc) : "l"(w), "l"(v));
}
__device__ __forceinline__ float f2sum(ull a) {
    return __uint_as_float((unsigned)(a & 0xffffffffull)) +
           __uint_as_float((unsigned)(a >> 32));
}
__device__ __forceinline__ float tanh_f(float x) {
    return 1.0f - __fdividef(2.0f, __expf(2.0f * x) + 1.0f);
}
__device__ __forceinline__ float sigm(float x) {
    return __fdividef(1.0f, 1.0f + __expf(-x));
}
__device__ __forceinline__ int slot_row(int s) { return (s & 3) * H + (s >> 2); }

// ---------------------------------------------------------------------------
// GEMM K=32 (layer-0 input part): 128 thr, 2 slots/thread.
// ---------------------------------------------------------------------------
__global__ void __launch_bounds__(128)
gemm_xg32(const float* __restrict__ X, const float* __restrict__ Wih,
          const float* __restrict__ bih, const float* __restrict__ bhh,
          float* __restrict__ out)
{
    constexpr int K = 32, ROWS = 128;
    __shared__ __align__(16) float xs[ROWS * K];

    const int tid = threadIdx.x;
    const int s0 = tid, s1 = tid + 128;
    const int r0 = slot_row(s0), r1 = slot_row(s1);

    ull w0[K / 2], w1[K / 2];
    #pragma unroll
    for (int i = 0; i < K / 2; i++) {
        w0[i] = reinterpret_cast<const ull*>(Wih + r0 * K)[i];
        w1[i] = reinterpret_cast<const ull*>(Wih + r1 * K)[i];
    }
    const float bias0 = bih[r0] + bhh[r0];
    const float bias1 = bih[r1] + bhh[r1];

    const size_t rowBase = (size_t)blockIdx.x * ROWS;
    const float4* src = reinterpret_cast<const float4*>(X + rowBase * K);
    float4* dst = reinterpret_cast<float4*>(xs);
    #pragma unroll
    for (int i = tid; i < ROWS * K / 4; i += 128) dst[i] = src[i];
    __syncthreads();

    #pragma unroll 4
    for (int row = 0; row < ROWS; row++) {
        const ulonglong2* xr = reinterpret_cast<const ulonglong2*>(xs + row * K);
        ull a0 = 0ull, a1 = 0ull;
        #pragma unroll
        for (int kk = 0; kk < K / 4; kk++) {
            ulonglong2 xv = xr[kk];
            ffma2(a0, w0[2 * kk], xv.x);  ffma2(a0, w0[2 * kk + 1], xv.y);
            ffma2(a1, w1[2 * kk], xv.x);  ffma2(a1, w1[2 * kk + 1], xv.y);
        }
        float* o = out + (rowBase + row) * NROWS;
        o[s0] = bias0 + f2sum(a0);
        o[s1] = bias1 + f2sum(a1);
    }
}

// ---------------------------------------------------------------------------
// A-phase layout (both rec kernels), 512 thr, NB=8, grid 128, 1 CTA/SM:
// lane bits: gp = b0, jlow = b2:1, q0 = b3, q1 = b4.  j = warp*4 + jlow.
// Thread holds 2 gate rows of j (gp=0: i,g ; gp=1: f,o) over K-quarter q.
// Butterfly xor8 (q0), xor16 (q1), xor1 (gp) lands the 4 complete gate
// pre-acts of batch b_own = 4*q1 + 2*q0 + gp on one lane, which owns c.
//
// FUSED B-phase (rec0 only): the same threads also compute
// xg1(t-1) = h1(t-1) @ W_ih1^T + bias from hs[cur] each step (lag-1).
// B layout: sp = warp*8 + (lane&7) -> slots {sp, sp+128}; K-quarter = q.
// Same xor8/xor16 combine; each lane finalizes 2 batches per 4-batch chunk.
// ---------------------------------------------------------------------------
__global__ void __launch_bounds__(512, 1)
lstm_rec0_fused(const float* __restrict__ xg,     // [BT][NROWS] xg0, bias in
                const float* __restrict__ Whh,    // W_hh0 [NROWS][H]
                const float* __restrict__ Wih1,   // W_ih1 [NROWS][H]
                const float* __restrict__ bih1,
                const float* __restrict__ bhh1,
                float* __restrict__ xg1out)       // [BT][NROWS]
{
    __shared__ __align__(16) float hs[2][8 * HP];

    const int tid  = threadIdx.x;
    const int lane = tid & 31;
    const int wrp  = tid >> 5;
    const int gp   = lane & 1;
    const int jlow = (lane >> 1) & 3;
    const int q    = (lane >> 3) & 3;
    const int q0   = q & 1, q1 = (q >> 1) & 1;
    const int j    = wrp * 4 + jlow;
    const int b_own = 4 * q1 + 2 * q0 + gp;
    const int b0   = blockIdx.x * 8;

    const int rA = gp * H + j;          // i (gp=0) / f (gp=1)
    const int rB = (gp + 2) * H + j;    // g (gp=0) / o (gp=1)

    ull wA[8], wB[8];
    #pragma unroll
    for (int i = 0; i < 8; i++) {
        wA[i] = reinterpret_cast<const ull*>(Whh + rA * H + q * 16)[i];
        wB[i] = reinterpret_cast<const ull*>(Whh + rB * H + q * 16)[i];
    }

    // B-phase setup: W_ih1 quarter-rows for slots sp, sp+128
    const int sp  = wrp * 8 + (lane & 7);
    const int rI0 = slot_row(sp), rI1 = rI0 + 32;
    ull wI0[8], wI1[8];
    #pragma unroll
    for (int i = 0; i < 8; i++) {
        wI0[i] = reinterpret_cast<const ull*>(Wih1 + rI0 * H + q * 16)[i];
        wI1[i] = reinterpret_cast<const ull*>(Wih1 + rI1 * H + q * 16)[i];
    }
    const float biasB0 = bih1[rI0] + bhh1[rI0];
    const float biasB1 = bih1[rI1] + bhh1[rI1];

    const float* xgp = xg + ((size_t)(b0 + b_own) * TT) * NROWS + j * 4;

    float c = 0.0f;
    for (int i = tid; i < 8 * HP; i += 512) hs[0][i] = 0.0f;

    float4 xg4 = *reinterpret_cast<const float4*>(xgp);
    __syncthreads();

    for (int t = 0; t < TT; t++) {
        const int cur = t & 1, nxt = cur ^ 1;

        float4 xg4n;
        if (t + 1 < TT)
            xg4n = *reinterpret_cast<const float4*>(xgp + (size_t)(t + 1) * NROWS);

        // ---- A: quarter-dots s[2 rows][8 batches] over hs[cur] ----
        float sA[8], sB[8];
        const float* hq = hs[cur] + q * 16;
        #pragma unroll
        for (int b = 0; b < 8; b++) {
            const ulonglong2* hb = reinterpret_cast<const ulonglong2*>(hq + b * HP);
            ulonglong2 h0 = hb[0], h1v = hb[1], h2 = hb[2], h3 = hb[3];
            ull aA = 0ull, aB = 0ull;
            ffma2(aA, wA[0], h0.x);  ffma2(aA, wA[1], h0.y);
            ffma2(aA, wA[2], h1v.x); ffma2(aA, wA[3], h1v.y);
            ffma2(aA, wA[4], h2.x);  ffma2(aA, wA[5], h2.y);
            ffma2(aA, wA[6], h3.x);  ffma2(aA, wA[7], h3.y);
            ffma2(aB, wB[0], h0.x);  ffma2(aB, wB[1], h0.y);
            ffma2(aB, wB[2], h1v.x); ffma2(aB, wB[3], h1v.y);
            ffma2(aB, wB[4], h2.x);  ffma2(aB, wB[5], h2.y);
            ffma2(aB, wB[6], h3.x);  ffma2(aB, wB[7], h3.y);
            sA[b] = f2sum(aA);
            sB[b] = f2sum(aB);
        }

        // ---- B: xg1(t-1) from hs[cur], 2 chunks of 4 batches ----
        const int tp = t - 1;
        #pragma unroll
        for (int ch = 0; ch < 2; ch++) {
            float v0[4], v1[4];
            #pragma unroll
            for (int bi = 0; bi < 4; bi++) {
                const ulonglong2* hb = reinterpret_cast<const ulonglong2*>(
                    hq + (4 * ch + bi) * HP);
                ulonglong2 h0 = hb[0], h1v = hb[1], h2 = hb[2], h3 = hb[3];
                ull a0 = 0ull, a1 = 0ull;
                ffma2(a0, wI0[0], h0.x);  ffma2(a0, wI0[1], h0.y);
                ffma2(a0, wI0[2], h1v.x); ffma2(a0, wI0[3], h1v.y);
                ffma2(a0, wI0[4], h2.x);  ffma2(a0, wI0[5], h2.y);
                ffma2(a0, wI0[6], h3.x);  ffma2(a0, wI0[7], h3.y);
                ffma2(a1, wI1[0], h0.x);  ffma2(a1, wI1[1], h0.y);
                ffma2(a1, wI1[2], h1v.x); ffma2(a1, wI1[3], h1v.y);
                ffma2(a1, wI1[4], h2.x);  ffma2(a1, wI1[5], h2.y);
                ffma2(a1, wI1[6], h3.x);  ffma2(a1, wI1[7], h3.y);
                v0[bi] = f2sum(a0);
                v1[bi] = f2sum(a1);
            }
            // xor8: keep b' = 2p + q0
            float t0[2], t1[2];
            #pragma unroll
            for (int p = 0; p < 2; p++) {
                float s0 = q0 ? v0[2 * p] : v0[2 * p + 1];
                float s1 = q0 ? v1[2 * p] : v1[2 * p + 1];
                float r0v = __shfl_xor_sync(0xffffffffu, s0, 8);
                float r1v = __shfl_xor_sync(0xffffffffu, s1, 8);
                t0[p] = (q0 ? v0[2 * p + 1] : v0[2 * p]) + r0v;
                t1[p] = (q0 ? v1[2 * p + 1] : v1[2 * p]) + r1v;
            }
            // xor16: keep b' = 2*q1 + q0
            float s0 = q1 ? t0[0] : t0[1];
            float s1 = q1 ? t1[0] : t1[1];
            float r0v = __shfl_xor_sync(0xffffffffu, s0, 16);
            float r1v = __shfl_xor_sync(0xffffffffu, s1, 16);
            float u0 = (q1 ? t0[1] : t0[0]) + r0v;
            float u1 = (q1 ? t1[1] : t1[0]) + r1v;

            if (tp >= 0) {
                int bb = b0 + 4 * ch + 2 * q1 + q0;
                size_t off = ((size_t)bb * TT + tp) * NROWS;
                xg1out[off + sp]       = biasB0 + u0;
                xg1out[off + sp + 128] = biasB1 + u1;
            }
        }

        // ---- A: butterfly + cell update ----
        float tA[4], tB[4];
        {
            #define RND1(sv, tv, x, y, pi)                                      \
                { float snd = q0 ? sv[x] : sv[y];                               \
                  float rcv = __shfl_xor_sync(0xffffffffu, snd, 8);             \
                  tv[pi] = (q0 ? sv[y] : sv[x]) + rcv; }
            RND1(sA, tA, 0, 2, 0) RND1(sA, tA, 1, 3, 1)
            RND1(sA, tA, 4, 6, 2) RND1(sA, tA, 5, 7, 3)
            RND1(sB, tB, 0, 2, 0) RND1(sB, tB, 1, 3, 1)
            RND1(sB, tB, 4, 6, 2) RND1(sB, tB, 5, 7, 3)
            #undef RND1
        }
        float uA[2], uB[2];
        {
            #define RND2(tv, uv, jj)                                            \
                { float snd = q1 ? tv[jj] : tv[jj + 2];                         \
                  float rcv = __shfl_xor_sync(0xffffffffu, snd, 16);            \
                  uv[jj] = (q1 ? tv[jj + 2] : tv[jj]) + rcv; }
            RND2(tA, uA, 0) RND2(tA, uA, 1)
            RND2(tB, uB, 0) RND2(tB, uB, 1)
            #undef RND2
        }
        float sendA = gp ? uA[0] : uA[1];
        float sendB = gp ? uB[0] : uB[1];
        float recvA = __shfl_xor_sync(0xffffffffu, sendA, 1);
        float recvB = __shfl_xor_sync(0xffffffffu, sendB, 1);
        float mineA = gp ? uA[1] : uA[0];
        float mineB = gp ? uB[1] : uB[0];

        float gi = (gp ? recvA : mineA) + xg4.x;
        float gf = (gp ? mineA : recvA) + xg4.y;
        float gg = (gp ? recvB : mineB) + xg4.z;
        float go = (gp ? mineB : recvB) + xg4.w;

        c = fmaf(sigm(gf), c, sigm(gi) * tanh_f(gg));
        float hh = sigm(go) * tanh_f(c);
        hs[nxt][b_own * HP + j] = hh;

        xg4 = xg4n;
        __syncthreads();
    }

    // B epilogue: xg1(TT-1) from hs[0] (TT even -> final h in hs[0])
    {
        const float* hq = hs[0] + q * 16;
        #pragma unroll
        for (int ch = 0; ch < 2; ch++) {
            float v0[4], v1[4];
            #pragma unroll
            for (int bi = 0; bi < 4; bi++) {
                const ulonglong2* hb = reinterpret_cast<const ulonglong2*>(
                    hq + (4 * ch + bi) * HP);
                ulonglong2 h0 = hb[0], h1v = hb[1], h2 = hb[2], h3 = hb[3];
                ull a0 = 0ull, a1 = 0ull;
                ffma2(a0, wI0[0], h0.x);  ffma2(a0, wI0[1], h0.y);
                ffma2(a0, wI0[2], h1v.x); ffma2(a0, wI0[3], h1v.y);
                ffma2(a0, wI0[4], h2.x);  ffma2(a0, wI0[5], h2.y);
                ffma2(a0, wI0[6], h3.x);  ffma2(a0, wI0[7], h3.y);
                ffma2(a1, wI1[0], h0.x);  ffma2(a1, wI1[1], h0.y);
                ffma2(a1, wI1[2], h1v.x); ffma2(a1, wI1[3], h1v.y);
                ffma2(a1, wI1[4], h2.x);  ffma2(a1, wI1[5], h2.y);
                ffma2(a1, wI1[6], h3.x);  ffma2(a1, wI1[7], h3.y);
                v0[bi] = f2sum(a0);
                v1[bi] = f2sum(a1);
            }
            float t0[2], t1[2];
            #pragma unroll
            for (int p = 0; p < 2; p++) {
                float s0 = q0 ? v0[2 * p] : v0[2 * p + 1];
                float s1 = q0 ? v1[2 * p] : v1[2 * p + 1];
                float r0v = __shfl_xor_sync(0xffffffffu, s0, 8);
                float r1v = __shfl_xor_sync(0xffffffffu, s1, 8);
                t0[p] = (q0 ? v0[2 * p + 1] : v0[2 * p]) + r0v;
                t1[p] = (q0 ? v1[2 * p + 1] : v1[2 * p]) + r1v;
            }
            float s0 = q1 ? t0[0] : t0[1];
            float s1 = q1 ? t1[0] : t1[1];
            float r0v = __shfl_xor_sync(0xffffffffu, s0, 16);
            float r1v = __shfl_xor_sync(0xffffffffu, s1, 16);
            float u0 = (q1 ? t0[1] : t0[0]) + r0v;
            float u1 = (q1 ? t1[1] : t1[0]) + r1v;

            int bb = b0 + 4 * ch + 2 * q1 + q0;
            size_t off = ((size_t)bb * TT + (TT - 1)) * NROWS;
            xg1out[off + sp]       = biasB0 + u0;
            xg1out[off + sp + 128] = biasB1 + u1;
        }
    }
}

// ---------------------------------------------------------------------------
// Layer-1 recurrent kernel: A-phase only (best-measured Round-7 shape) + FC.
// ---------------------------------------------------------------------------
__global__ void __launch_bounds__(512, 1)
lstm_rec1(const float* __restrict__ xg,    // xg1 [BT][NROWS], bias folded in
          const float* __restrict__ Whh,   // W_hh1
          const float* __restrict__ Wfc,
          const float* __restrict__ bfc,
          float* __restrict__ out)
{
    __shared__ __align__(16) float hs[2][8 * HP];

    const int tid  = threadIdx.x;
    const int lane = tid & 31;
    const int wrp  = tid >> 5;
    const int gp   = lane & 1;
    const int jlow = (lane >> 1) & 3;
    const int q    = (lane >> 3) & 3;
    const int q0   = q & 1, q1 = (q >> 1) & 1;
    const int j    = wrp * 4 + jlow;
    const int b_own = 4 * q1 + 2 * q0 + gp;
    const int b0   = blockIdx.x * 8;

    const int rA = gp * H + j;
    const int rB = (gp + 2) * H + j;

    ull wA[8], wB[8];
    #pragma unroll
    for (int i = 0; i < 8; i++) {
        wA[i] = reinterpret_cast<const ull*>(Whh + rA * H + q * 16)[i];
        wB[i] = reinterpret_cast<const ull*>(Whh + rB * H + q * 16)[i];
    }

    const float* xgp = xg + ((size_t)(b0 + b_own) * TT) * NROWS + j * 4;

    float c = 0.0f;
    for (int i = tid; i < 8 * HP; i += 512) hs[0][i] = 0.0f;

    float4 xg4 = *reinterpret_cast<const float4*>(xgp);
    __syncthreads();

    for (int t = 0; t < TT; t++) {
        const int cur = t & 1, nxt = cur ^ 1;

        float4 xg4n;
        if (t + 1 < TT)
            xg4n = *reinterpret_cast<const float4*>(xgp + (size_t)(t + 1) * NROWS);

        float sA[8], sB[8];
        const float* hq = hs[cur] + q * 16;
        #pragma unroll
        for (int b = 0; b < 8; b++) {
            const ulonglong2* hb = reinterpret_cast<const ulonglong2*>(hq + b * HP);
            ulonglong2 h0 = hb[0], h1v = hb[1], h2 = hb[2], h3 = hb[3];
            ull aA = 0ull, aB = 0ull;
            ffma2(aA, wA[0], h0.x);  ffma2(aA, wA[1], h0.y);
            ffma2(aA, wA[2], h1v.x); ffma2(aA, wA[3], h1v.y);
            ffma2(aA, wA[4], h2.x);  ffma2(aA, wA[5], h2.y);
            ffma2(aA, wA[6], h3.x);  ffma2(aA, wA[7], h3.y);
            ffma2(aB, wB[0], h0.x);  ffma2(aB, wB[1], h0.y);
            ffma2(aB, wB[2], h1v.x); ffma2(aB, wB[3], h1v.y);
            ffma2(aB, wB[4], h2.x);  ffma2(aB, wB[5], h2.y);
            ffma2(aB, wB[6], h3.x);  ffma2(aB, wB[7], h3.y);
            sA[b] = f2sum(aA);
            sB[b] = f2sum(aB);
        }

        float tA[4], tB[4];
        {
            #define RND1(sv, tv, x, y, pi)                                      \
                { float snd = q0 ? sv[x] : sv[y];                               \
                  float rcv = __shfl_xor_sync(0xffffffffu, snd, 8);             \
                  tv[pi] = (q0 ? sv[y] : sv[x]) + rcv; }
            RND1(sA, tA, 0, 2, 0) RND1(sA, tA, 1, 3, 1)
            RND1(sA, tA, 4, 6, 2) RND1(sA, tA, 5, 7, 3)
            RND1(sB, tB, 0, 2, 0) RND1(sB, tB, 1, 3, 1)
            RND1(sB, tB, 4, 6, 2) RND1(sB, tB, 5, 7, 3)
            #undef RND1
        }
        float uA[2], uB[2];
        {
            #define RND2(tv, uv, jj)                                            \
                { float snd = q1 ? tv[jj] : tv[jj + 2];                         \
                  float rcv = __shfl_xor_sync(0xffffffffu, snd, 16);            \
                  uv[jj] = (q1 ? tv[jj + 2] : tv[jj]) + rcv; }
            RND2(tA, uA, 0) RND2(tA, uA, 1)
            RND2(tB, uB, 0) RND2(tB, uB, 1)
            #undef RND2
        }
        float sendA = gp ? uA[0] : uA[1];
        float sendB = gp ? uB[0] : uB[1];
        float recvA = __shfl_xor_sync(0xffffffffu, sendA, 1);
        float recvB = __shfl_xor_sync(0xffffffffu, sendB, 1);
        float mineA = gp ? uA[1] : uA[0];
        float mineB = gp ? uB[1] : uB[0];

        float gi = (gp ? recvA : mineA) + xg4.x;
        float gf = (gp ? mineA : recvA) + xg4.y;
        float gg = (gp ? recvB : mineB) + xg4.z;
        float go = (gp ? mineB : recvB) + xg4.w;

        c = fmaf(sigm(gf), c, sigm(gi) * tanh_f(gg));
        float hh = sigm(go) * tanh_f(c);
        hs[nxt][b_own * HP + j] = hh;

        xg4 = xg4n;
        __syncthreads();
    }

    if (tid < 8) {
        float a = bfc[0];
        #pragma unroll
        for (int k = 0; k < H; k++) a = fmaf(hs[0][tid * HP + k], Wfc[k], a);
        out[b0 + tid] = a;
    }
}

// ---------------------------------------------------------------------------
extern "C" void kernel_launch(void* const* d_in, const int* in_sizes, int n_in,
                              void* d_out, int out_size)
{
    const float* x    = (const float*)d_in[0];
    const float* Wih0 = (const float*)d_in[1];
    const float* Whh0 = (const float*)d_in[2];
    const float* bih0 = (const float*)d_in[3];
    const float* bhh0 = (const float*)d_in[4];
    const float* Wih1 = (const float*)d_in[5];
    const float* Whh1 = (const float*)d_in[6];
    const float* bih1 = (const float*)d_in[7];
    const float* bhh1 = (const float*)d_in[8];
    const float* Wfc  = (const float*)d_in[9];
    const float* bfc  = (const float*)d_in[10];
    float* out = (float*)d_out;

    float *xg0, *xg1;
    cudaGetSymbolAddress((void**)&xg0, g_xg0);
    cudaGetSymbolAddress((void**)&xg1, g_xg1);

    gemm_xg32<<<BT / 128, 128>>>(x, Wih0, bih0, bhh0, xg0);
    lstm_rec0_fused<<<BATCH / 8, 512>>>(xg0, Whh0, Wih1, bih1, bhh1, xg1);
    lstm_rec1<<<BATCH / 8, 512>>>(xg1, Whh1, Wfc, bfc, out);
}

// round 15
// speedup vs baseline: 1.4342x; 1.4342x over previous
// R13 = R10 source, third submission attempt. R11/R12 failed with
// "GB300 container failed twice" — container acquisition error, no kernel
// evidence produced. If this fails too, next round reverts to R7 source to
// test content-dependence of the infra failure.
#include <cuda_runtime.h>

#define BATCH 1024
#define TT    512
#define DIN   32
#define H     64
#define NROWS 256
#define BT    (BATCH * TT)
#define HP    68          // padded h row stride (conflict-free)

typedef unsigned long long ull;

__device__ float g_xg0[(size_t)BT * NROWS];
__device__ float g_xg1[(size_t)BT * NROWS];
__device__ float g_h1 [(size_t)BT * H];

// ---------------------------------------------------------------------------
__device__ __forceinline__ void ffma2(ull& acc, ull w, ull v) {
    asm("fma.rn.f32x2 %0, %1, %2, %0;" : "+l"(acc) : "l"(w), "l"(v));
}
__device__ __forceinline__ float f2sum(ull a) {
    return __uint_as_float((unsigned)(a & 0xffffffffull)) +
           __uint_as_float((unsigned)(a >> 32));
}
__device__ __forceinline__ float tanh_f(float x) {
    return 1.0f - __fdividef(2.0f, __expf(2.0f * x) + 1.0f);
}
__device__ __forceinline__ float sigm(float x) {
    return __fdividef(1.0f, 1.0f + __expf(-x));
}

// ---------------------------------------------------------------------------
// GEMM K=32, layer-0 input part. 128 thr = 64 j x 2 half-K.
// Thread holds 4 gate rows of j over 16 k (32 ull regs). xor1 combine;
// lane with half == (row&1) writes the float4 (i,f,g,o of j): 1 STG.128.
// ---------------------------------------------------------------------------
__global__ void __launch_bounds__(128)
gemm_xg32(const float* __restrict__ X, const float* __restrict__ Wih,
          const float* __restrict__ bih, const float* __restrict__ bhh,
          float* __restrict__ out)
{
    constexpr int K = 32, ROWS = 128;
    __shared__ __align__(16) float xs[ROWS * K];

    const int tid  = threadIdx.x;
    const int half = tid & 1;
    const int j    = tid >> 1;

    ull w[4][8];
    float bias[4];
    #pragma unroll
    for (int g = 0; g < 4; g++) {
        const int r = g * H + j;
        const ull* ws = reinterpret_cast<const ull*>(Wih + r * K + half * 16);
        #pragma unroll
        for (int i = 0; i < 8; i++) w[g][i] = ws[i];
        bias[g] = bih[r] + bhh[r];
    }

    const size_t rowBase = (size_t)blockIdx.x * ROWS;
    const float4* src = reinterpret_cast<const float4*>(X + rowBase * K);
    float4* dst = reinterpret_cast<float4*>(xs);
    #pragma unroll
    for (int i = tid; i < ROWS * K / 4; i += 128) dst[i] = src[i];
    __syncthreads();

    #pragma unroll 2
    for (int row = 0; row < ROWS; row++) {
        const ulonglong2* xr =
            reinterpret_cast<const ulonglong2*>(xs + row * K + half * 16);
        ulonglong2 x0 = xr[0], x1 = xr[1];
        const ulonglong2* xr2 = xr + 2;
        ulonglong2 x2 = xr2[0], x3 = xr2[1];
        float s[4];
        #pragma unroll
        for (int g = 0; g < 4; g++) {
            ull a = 0ull;
            ffma2(a, w[g][0], x0.x); ffma2(a, w[g][1], x0.y);
            ffma2(a, w[g][2], x1.x); ffma2(a, w[g][3], x1.y);
            ffma2(a, w[g][4], x2.x); ffma2(a, w[g][5], x2.y);
            ffma2(a, w[g][6], x3.x); ffma2(a, w[g][7], x3.y);
            s[g] = f2sum(a);
        }
        #pragma unroll
        for (int g = 0; g < 4; g++)
            s[g] += __shfl_xor_sync(0xffffffffu, s[g], 1);

        if (half == (row & 1)) {
            float4 o;
            o.x = bias[0] + s[0]; o.y = bias[1] + s[1];
            o.z = bias[2] + s[2]; o.w = bias[3] + s[3];
            *reinterpret_cast<float4*>(out + (rowBase + row) * NROWS + j * 4) = o;
        }
    }
}

// ---------------------------------------------------------------------------
// GEMM K=64, layer-1 input part. 256 thr = 64 j x 4 quarter-K.
// Thread holds 4 gate rows of j over 16 k (32 ull regs). xor1+xor2 combine;
// lane with q == (row&3) writes the float4: 1 STG.128 per 4 rows.
// ---------------------------------------------------------------------------
__global__ void __launch_bounds__(256)
gemm_xg64(const float* __restrict__ X, const float* __restrict__ Wih,
          const float* __restrict__ bih, const float* __restrict__ bhh,
          float* __restrict__ out)
{
    constexpr int K = 64, ROWS = 128;
    __shared__ __align__(16) float xs[ROWS * K];   // 32 KB

    const int tid = threadIdx.x;
    const int q   = tid & 3;
    const int j   = tid >> 2;

    ull w[4][8];
    float bias[4];
    #pragma unroll
    for (int g = 0; g < 4; g++) {
        const int r = g * H + j;
        const ull* ws = reinterpret_cast<const ull*>(Wih + r * K + q * 16);
        #pragma unroll
        for (int i = 0; i < 8; i++) w[g][i] = ws[i];
        bias[g] = bih[r] + bhh[r];
    }

    const size_t rowBase = (size_t)blockIdx.x * ROWS;
    const float4* src = reinterpret_cast<const float4*>(X + rowBase * K);
    float4* dst = reinterpret_cast<float4*>(xs);
    #pragma unroll
    for (int i = tid; i < ROWS * K / 4; i += 256) dst[i] = src[i];
    __syncthreads();

    #pragma unroll 2
    for (int row = 0; row < ROWS; row++) {
        const ulonglong2* xr =
            reinterpret_cast<const ulonglong2*>(xs + row * K + q * 16);
        ulonglong2 x0 = xr[0], x1 = xr[1], x2 = xr[2], x3 = xr[3];
        float s[4];
        #pragma unroll
        for (int g = 0; g < 4; g++) {
            ull a = 0ull;
            ffma2(a, w[g][0], x0.x); ffma2(a, w[g][1], x0.y);
            ffma2(a, w[g][2], x1.x); ffma2(a, w[g][3], x1.y);
            ffma2(a, w[g][4], x2.x); ffma2(a, w[g][5], x2.y);
            ffma2(a, w[g][6], x3.x); ffma2(a, w[g][7], x3.y);
            s[g] = f2sum(a);
        }
        #pragma unroll
        for (int g = 0; g < 4; g++) {
            s[g] += __shfl_xor_sync(0xffffffffu, s[g], 1);
            s[g] += __shfl_xor_sync(0xffffffffu, s[g], 2);
        }
        if (q == (row & 3)) {
            float4 o;
            o.x = bias[0] + s[0]; o.y = bias[1] + s[1];
            o.z = bias[2] + s[2]; o.w = bias[3] + s[3];
            *reinterpret_cast<float4*>(out + (rowBase + row) * NROWS + j * 4) = o;
        }
    }
}

// ---------------------------------------------------------------------------
// Recurrent kernel (best measured: 600.8 us): 512 thr, NB=8, grid 128.
// lane bits: gp = b0, jlow = b2:1, q0 = b3, q1 = b4.  j = warp*4 + jlow.
// Thread holds 2 gate rows of j over K-quarter q; butterfly xor8/xor16/xor1
// lands the 4 gate pre-acts of batch b_own = 4*q1 + 2*q0 + gp on one lane.
// ---------------------------------------------------------------------------
template <bool FIRST>
__global__ void __launch_bounds__(512, 1)
lstm_rec(const float* __restrict__ xg,    // [BT][NROWS], bias folded in
         const float* __restrict__ Whh,   // [NROWS][H]
         float* __restrict__ h1out,
         const float* __restrict__ Wfc,
         const float* __restrict__ bfc,
         float* __restrict__ out)
{
    __shared__ __align__(16) float hs[2][8 * HP];

    const int tid  = threadIdx.x;
    const int lane = tid & 31;
    const int wrp  = tid >> 5;
    const int gp   = lane & 1;
    const int jlow = (lane >> 1) & 3;
    const int q    = (lane >> 3) & 3;
    const int q0   = q & 1, q1 = (q >> 1) & 1;
    const int j    = wrp * 4 + jlow;
    const int b_own = 4 * q1 + 2 * q0 + gp;
    const int b0   = blockIdx.x * 8;

    const int rA = gp * H + j;          // i (gp=0) / f (gp=1)
    const int rB = (gp + 2) * H + j;    // g (gp=0) / o (gp=1)

    ull wA[8], wB[8];
    #pragma unroll
    for (int i = 0; i < 8; i++) {
        wA[i] = reinterpret_cast<const ull*>(Whh + rA * H + q * 16)[i];
        wB[i] = reinterpret_cast<const ull*>(Whh + rB * H + q * 16)[i];
    }

    const float* xgp = xg + ((size_t)(b0 + b_own) * TT) * NROWS + j * 4;
    float* h1p = FIRST ? (h1out + ((size_t)(b0 + b_own) * TT) * H + j) : nullptr;

    float c = 0.0f;
    for (int i = tid; i < 8 * HP; i += 512) hs[0][i] = 0.0f;

    float4 xg4 = *reinterpret_cast<const float4*>(xgp);
    __syncthreads();

    for (int t = 0; t < TT; t++) {
        const int cur = t & 1, nxt = cur ^ 1;

        float4 xg4n;
        if (t + 1 < TT)
            xg4n = *reinterpret_cast<const float4*>(xgp + (size_t)(t + 1) * NROWS);

        float sA[8], sB[8];
        const float* hq = hs[cur] + q * 16;
        #pragma unroll
        for (int b = 0; b < 8; b++) {
            const ulonglong2* hb = reinterpret_cast<const ulonglong2*>(hq + b * HP);
            ulonglong2 h0 = hb[0], h1v = hb[1], h2 = hb[2], h3 = hb[3];
            ull aA = 0ull, aB = 0ull;
            ffma2(aA, wA[0], h0.x);  ffma2(aA, wA[1], h0.y);
            ffma2(aA, wA[2], h1v.x); ffma2(aA, wA[3], h1v.y);
            ffma2(aA, wA[4], h2.x);  ffma2(aA, wA[5], h2.y);
            ffma2(aA, wA[6], h3.x);  ffma2(aA, wA[7], h3.y);
            ffma2(aB, wB[0], h0.x);  ffma2(aB, wB[1], h0.y);
            ffma2(aB, wB[2], h1v.x); ffma2(aB, wB[3], h1v.y);
            ffma2(aB, wB[4], h2.x);  ffma2(aB, wB[5], h2.y);
            ffma2(aB, wB[6], h3.x);  ffma2(aB, wB[7], h3.y);
            sA[b] = f2sum(aA);
            sB[b] = f2sum(aB);
        }

        float tA[4], tB[4];
        {
            #define RND1(sv, tv, x, y, pi)                                      \
                { float snd = q0 ? sv[x] : sv[y];                               \
                  float rcv = __shfl_xor_sync(0xffffffffu, snd, 8);             \
                  tv[pi] = (q0 ? sv[y] : sv[x]) + rcv; }
            RND1(sA, tA, 0, 2, 0) RND1(sA, tA, 1, 3, 1)
            RND1(sA, tA, 4, 6, 2) RND1(sA, tA, 5, 7, 3)
            RND1(sB, tB, 0, 2, 0) RND1(sB, tB, 1, 3, 1)
            RND1(sB, tB, 4, 6, 2) RND1(sB, tB, 5, 7, 3)
            #undef RND1
        }
        float uA[2], uB[2];
        {
            #define RND2(tv, uv, jj)                                            \
                { float snd = q1 ? tv[jj] : tv[jj + 2];                         \
                  float rcv = __shfl_xor_sync(0xffffffffu, snd, 16);            \
                  uv[jj] = (q1 ? tv[jj + 2] : tv[jj]) + rcv; }
            RND2(tA, uA, 0) RND2(tA, uA, 1)
            RND2(tB, uB, 0) RND2(tB, uB, 1)
            #undef RND2
        }
        float sendA = gp ? uA[0] : uA[1];
        float sendB = gp ? uB[0] : uB[1];
        float recvA = __shfl_xor_sync(0xffffffffu, sendA, 1);
        float recvB = __shfl_xor_sync(0xffffffffu, sendB, 1);
        float mineA = gp ? uA[1] : uA[0];
        float mineB = gp ? uB[1] : uB[0];

        float gi = (gp ? recvA : mineA) + xg4.x;
        float gf = (gp ? mineA : recvA) + xg4.y;
        float gg = (gp ? recvB : mineB) + xg4.z;
        float go = (gp ? mineB : recvB) + xg4.w;

        c = fmaf(sigm(gf), c, sigm(gi) * tanh_f(gg));
        float hh = sigm(go) * tanh_f(c);
        hs[nxt][b_own * HP + j] = hh;
        if (FIRST) h1p[(size_t)t * H] = hh;

        xg4 = xg4n;
        __syncthreads();
    }

    if (!FIRST && tid < 8) {
        float a = bfc[0];
        #pragma unroll
        for (int k = 0; k < H; k++) a = fmaf(hs[0][tid * HP + k], Wfc[k], a);
        out[b0 + tid] = a;
    }
}

// ---------------------------------------------------------------------------
extern "C" void kernel_launch(void* const* d_in, const int* in_sizes, int n_in,
                              void* d_out, int out_size)
{
    const float* x    = (const float*)d_in[0];
    const float* Wih0 = (const float*)d_in[1];
    const float* Whh0 = (const float*)d_in[2];
    const float* bih0 = (const float*)d_in[3];
    const float* bhh0 = (const float*)d_in[4];
    const float* Wih1 = (const float*)d_in[5];
    const float* Whh1 = (const float*)d_in[6];
    const float* bih1 = (const float*)d_in[7];
    const float* bhh1 = (const float*)d_in[8];
    const float* Wfc  = (const float*)d_in[9];
    const float* bfc  = (const float*)d_in[10];
    float* out = (float*)d_out;

    float *xg0, *xg1, *h1;
    cudaGetSymbolAddress((void**)&xg0, g_xg0);
    cudaGetSymbolAddress((void**)&xg1, g_xg1);
    cudaGetSymbolAddress((void**)&h1,  g_h1);

    gemm_xg32<<<BT / 128, 128>>>(x, Wih0, bih0, bhh0, xg0);
    lstm_rec<true><<<BATCH / 8, 512>>>(xg0, Whh0, h1, nullptr, nullptr, nullptr);
    gemm_xg64<<<BT / 128, 256>>>(h1, Wih1, bih1, bhh1, xg1);
    lstm_rec<false><<<BATCH / 8, 512>>>(xg1, Whh1, nullptr, Wfc, bfc, out);
}